// round 9
// baseline (speedup 1.0000x reference)
#include <cuda_runtime.h>
#include <cstdint>
#include <math.h>

// ---------------- problem constants ------------------------------------------
#define NTOK 8192
#define CDIM 1024
#define HDIM 2048
#define NEXP 8
#define NPAIR (NTOK * 2)
#define BM 128
#define MT_MAX 136
#define QMAX 16256.0f

// ---------------- scratch ----------------------------------------------------
__device__ int8_t g_aIH[(size_t)NPAIR * CDIM];
__device__ int8_t g_aIL[(size_t)NPAIR * CDIM];
__device__ float  g_sA[NPAIR];
__device__ int8_t g_wgIH[(size_t)NEXP * HDIM * CDIM];
__device__ int8_t g_wgIL[(size_t)NEXP * HDIM * CDIM];
__device__ int8_t g_wiIH[(size_t)NEXP * HDIM * CDIM];
__device__ int8_t g_wiIL[(size_t)NEXP * HDIM * CDIM];
__device__ int8_t g_woIH[(size_t)NEXP * CDIM * HDIM];
__device__ int8_t g_woIL[(size_t)NEXP * CDIM * HDIM];
__device__ float  g_sWg[NEXP * HDIM];
__device__ float  g_sWi[NEXP * HDIM];
__device__ float  g_sWo[NEXP * CDIM];
__device__ float  g_gf[(size_t)NPAIR * HDIM];
__device__ float  g_hf[(size_t)NPAIR * HDIM];
__device__ int8_t g_hIH[(size_t)NPAIR * HDIM];
__device__ int8_t g_hIL[(size_t)NPAIR * HDIM];
__device__ float  g_sH[NPAIR];
__device__ float  g_y[(size_t)NPAIR * CDIM];

__device__ int   g_sel[NTOK * 2];
__device__ float g_selw[NTOK * 2];
__device__ int   g_tok[NPAIR];
__device__ float g_wt[NPAIR];
__device__ int   g_pairidx[NTOK * 2];
__device__ int   g_cnt[NEXP];
__device__ int   g_off[NEXP];
__device__ int   g_tileE[MT_MAX];
__device__ int   g_tileR[MT_MAX];
__device__ int   g_numTiles;

// ---------------- PTX helpers -------------------------------------------------
__device__ __forceinline__ uint32_t smem_u32(const void* p) {
    uint32_t a;
    asm("{ .reg .u64 t; cvta.to.shared.u64 t, %1; cvt.u32.u64 %0, t; }" : "=r"(a) : "l"(p));
    return a;
}
__device__ __forceinline__ void ldsm4(uint32_t* r, uint32_t addr) {
    asm volatile("ldmatrix.sync.aligned.m8n8.x4.shared.b16 {%0,%1,%2,%3}, [%4];"
                 : "=r"(r[0]), "=r"(r[1]), "=r"(r[2]), "=r"(r[3]) : "r"(addr));
}
__device__ __forceinline__ void mma_s8(int32_t* d, const uint32_t* a, uint32_t b0, uint32_t b1) {
    asm volatile("mma.sync.aligned.m16n8k32.row.col.s32.s8.s8.s32 "
                 "{%0,%1,%2,%3}, {%4,%5,%6,%7}, {%8,%9}, {%0,%1,%2,%3};"
                 : "+r"(d[0]), "+r"(d[1]), "+r"(d[2]), "+r"(d[3])
                 : "r"(a[0]), "r"(a[1]), "r"(a[2]), "r"(a[3]), "r"(b0), "r"(b1));
}
#define CP_ASYNC16(dst, src, sz) \
    asm volatile("cp.async.cg.shared.global [%0], [%1], 16, %2;" :: "r"(dst), "l"(src), "r"(sz) : "memory")
#define CP_COMMIT() asm volatile("cp.async.commit_group;" ::: "memory")
#define CP_WAIT(n)  asm volatile("cp.async.wait_group %0;" :: "n"(n) : "memory")

__device__ __forceinline__ void quant15(float v, float inv, int& IH, int& IL) {
    int I = __float2int_rn(v * inv);
    IH = (I + 64) >> 7;            // arithmetic shift floors
    IL = I - (IH << 7);            // IL in [-64, 64]
}

// ---------------- gating -----------------------------------------------------
__global__ void gate_kernel(const float* __restrict__ x, const float* __restrict__ wgate) {
    int warp = (blockIdx.x * blockDim.x + threadIdx.x) >> 5;
    int lane = threadIdx.x & 31;
    if (warp >= NTOK) return;
    const float* xr = x + (size_t)warp * CDIM;
    float acc[NEXP];
#pragma unroll
    for (int e = 0; e < NEXP; e++) acc[e] = 0.f;
    for (int i = lane * 4; i < CDIM; i += 128) {
        float4 xv = *(const float4*)(xr + i);
        float xs[4] = {xv.x, xv.y, xv.z, xv.w};
#pragma unroll
        for (int j = 0; j < 4; j++) {
            const float* wr = wgate + (size_t)(i + j) * NEXP;
#pragma unroll
            for (int e = 0; e < NEXP; e++) acc[e] += xs[j] * wr[e];
        }
    }
#pragma unroll
    for (int e = 0; e < NEXP; e++)
#pragma unroll
        for (int d = 16; d > 0; d >>= 1) acc[e] += __shfl_down_sync(0xffffffffu, acc[e], d);
    if (lane == 0) {
        float m = acc[0];
#pragma unroll
        for (int e = 1; e < NEXP; e++) m = fmaxf(m, acc[e]);
        float p[NEXP]; float s = 0.f;
#pragma unroll
        for (int e = 0; e < NEXP; e++) { p[e] = expf(acc[e] - m); s += p[e]; }
        float inv = 1.f / s;
#pragma unroll
        for (int e = 0; e < NEXP; e++) p[e] *= inv;
        int i1 = 0;
#pragma unroll
        for (int e = 1; e < NEXP; e++) if (p[e] > p[i1]) i1 = e;
        int i2 = (i1 == 0) ? 1 : 0;
#pragma unroll
        for (int e = 0; e < NEXP; e++) if (e != i1 && p[e] > p[i2]) i2 = e;
        g_sel[2 * warp] = i1;     g_selw[2 * warp] = p[i1];
        g_sel[2 * warp + 1] = i2; g_selw[2 * warp + 1] = p[i2];
    }
}

// ---------------- routing build ----------------------------------------------
__global__ void setup_kernel() {
    __shared__ int scnt[NEXP], soff[NEXP], wsum[8];
    __shared__ int carry_s;
    int tid = threadIdx.x, lane = tid & 31, wid = tid >> 5;
    if (tid < NEXP) scnt[tid] = 0;
    __syncthreads();
    for (int t = tid; t < NTOK; t += 256) {
        atomicAdd(&scnt[g_sel[2 * t]], 1);
        atomicAdd(&scnt[g_sel[2 * t + 1]], 1);
    }
    __syncthreads();
    if (tid == 0) {
        int o = 0, nt = 0;
        for (int e = 0; e < NEXP; e++) {
            g_cnt[e] = scnt[e]; g_off[e] = o; soff[e] = o;
            for (int r = 0; r < scnt[e]; r += BM) { g_tileE[nt] = e; g_tileR[nt] = r; nt++; }
            o += scnt[e];
        }
        g_numTiles = nt;
    }
    __syncthreads();
    for (int e = 0; e < NEXP; e++) {
        if (tid == 0) carry_s = 0;
        __syncthreads();
        int base_off = soff[e];
        for (int base = 0; base < NTOK; base += 256) {
            int t = base + tid;
            int slot = (g_sel[2 * t] == e) ? 0 : ((g_sel[2 * t + 1] == e) ? 1 : -1);
            int f = (slot >= 0) ? 1 : 0;
            int v = f;
#pragma unroll
            for (int d = 1; d < 32; d <<= 1) {
                int u = __shfl_up_sync(0xffffffffu, v, d);
                if (lane >= d) v += u;
            }
            if (lane == 31) wsum[wid] = v;
            __syncthreads();
            int wbase = 0, tot = 0;
#pragma unroll
            for (int w = 0; w < 8; w++) { if (w < wid) wbase += wsum[w]; tot += wsum[w]; }
            if (f) {
                int p = base_off + carry_s + wbase + v - 1;
                g_tok[p] = t;
                g_wt[p] = g_selw[2 * t + slot];
                g_pairidx[2 * t + slot] = p;
            }
            __syncthreads();
            if (tid == 0) carry_s += tot;
            __syncthreads();
        }
    }
}

// ---------------- activation gather + int8 digit quantization -----------------
__global__ void xquant_kernel(const float* __restrict__ x) {
    __shared__ float red[256];
    int p = blockIdx.x, tid = threadIdx.x;
    int t = g_tok[p];
    float4 v = ((const float4*)(x + (size_t)t * CDIM))[tid];
    float m = fmaxf(fmaxf(fabsf(v.x), fabsf(v.y)), fmaxf(fabsf(v.z), fabsf(v.w)));
    red[tid] = m; __syncthreads();
    for (int s = 128; s > 0; s >>= 1) { if (tid < s) red[tid] = fmaxf(red[tid], red[tid + s]); __syncthreads(); }
    float mx = fmaxf(red[0], 1e-20f);
    float inv = QMAX / mx;
    if (tid == 0) g_sA[p] = mx / QMAX;
    float vs[4] = {v.x, v.y, v.z, v.w};
    uint32_t uh = 0, ul = 0;
#pragma unroll
    for (int i = 0; i < 4; i++) {
        int IH, IL; quant15(vs[i], inv, IH, IL);
        uh |= ((uint32_t)(IH & 0xff)) << (8 * i);
        ul |= ((uint32_t)(IL & 0xff)) << (8 * i);
    }
    ((uint32_t*)(g_aIH + (size_t)p * CDIM))[tid] = uh;
    ((uint32_t*)(g_aIL + (size_t)p * CDIM))[tid] = ul;
}

// ---------------- h quantization ----------------------------------------------
__global__ void hquant_kernel() {
    __shared__ float red[256];
    int p = blockIdx.x, tid = threadIdx.x;
    const float4* hr = (const float4*)(g_hf + (size_t)p * HDIM);
    float4 v0 = hr[tid], v1 = hr[tid + 256];
    float m = fmaxf(fmaxf(fabsf(v0.x), fabsf(v0.y)), fmaxf(fabsf(v0.z), fabsf(v0.w)));
    m = fmaxf(m, fmaxf(fmaxf(fabsf(v1.x), fabsf(v1.y)), fmaxf(fabsf(v1.z), fabsf(v1.w))));
    red[tid] = m; __syncthreads();
    for (int s = 128; s > 0; s >>= 1) { if (tid < s) red[tid] = fmaxf(red[tid], red[tid + s]); __syncthreads(); }
    float mx = fmaxf(red[0], 1e-20f);
    float inv = QMAX / mx;
    if (tid == 0) g_sH[p] = mx / QMAX;
    float vs0[4] = {v0.x, v0.y, v0.z, v0.w};
    float vs1[4] = {v1.x, v1.y, v1.z, v1.w};
    uint32_t uh0 = 0, ul0 = 0, uh1 = 0, ul1 = 0;
#pragma unroll
    for (int i = 0; i < 4; i++) {
        int IH, IL;
        quant15(vs0[i], inv, IH, IL);
        uh0 |= ((uint32_t)(IH & 0xff)) << (8 * i);
        ul0 |= ((uint32_t)(IL & 0xff)) << (8 * i);
        quant15(vs1[i], inv, IH, IL);
        uh1 |= ((uint32_t)(IH & 0xff)) << (8 * i);
        ul1 |= ((uint32_t)(IL & 0xff)) << (8 * i);
    }
    uint32_t* dH = (uint32_t*)(g_hIH + (size_t)p * HDIM);
    uint32_t* dL = (uint32_t*)(g_hIL + (size_t)p * HDIM);
    dH[tid] = uh0; dH[tid + 256] = uh1;
    dL[tid] = ul0; dL[tid + 256] = ul1;
}

// ---------------- weight transpose + quantize ---------------------------------
// src [E][KD][S] fp32 -> digits [E][S][KD] int8 (K-contiguous), per-s scales.
// W: 0=wg, 1=wi, 2=wo. Dest selected in device code (ATS pitfall!).
template <int W>
__global__ void wquant_kernel(const float* __restrict__ src, int S) {
    constexpr int KD = (W == 2) ? HDIM : CDIM;
    constexpr int SW = (W == 2) ? 16 : 32;
    constexpr int PAD = SW + 1;
    constexpr int RPG = 256 / SW;      // k-rows per thread group
    int8_t* dH = (W == 0) ? g_wgIH : (W == 1) ? g_wiIH : g_woIH;
    int8_t* dL = (W == 0) ? g_wgIL : (W == 1) ? g_wiIL : g_woIL;
    float* sW  = (W == 0) ? g_sWg  : (W == 1) ? g_sWi  : g_sWo;

    extern __shared__ float tile[];    // [KD][PAD]
    __shared__ float red[256];
    __shared__ float scol[SW];

    int e = blockIdx.y, s0 = blockIdx.x * SW;
    int tid = threadIdx.x;
    const float* sp = src + (size_t)e * KD * S + s0;

    for (int idx = tid; idx < KD * SW; idx += 256) {
        int k = idx / SW, s = idx % SW;
        tile[k * PAD + s] = sp[(size_t)k * S + s];
    }
    __syncthreads();

    {
        int s = tid % SW, kg = tid / SW;
        float m = 0.f;
        for (int k = kg; k < KD; k += RPG) m = fmaxf(m, fabsf(tile[k * PAD + s]));
        red[tid] = m;
    }
    __syncthreads();
    if (tid < SW) {
        float m = red[tid];
#pragma unroll
        for (int j = 1; j < RPG; j++) m = fmaxf(m, red[tid + j * SW]);
        m = fmaxf(m, 1e-20f);
        scol[tid] = QMAX / m;
        sW[e * S + s0 + tid] = m / QMAX;
    }
    __syncthreads();

    for (int idx = tid; idx < KD * SW; idx += 256) {
        int c = idx / KD, k = idx % KD;
        float v = tile[k * PAD + c];
        int IH, IL; quant15(v, scol[c], IH, IL);
        size_t o = ((size_t)e * S + s0 + c) * KD + k;
        dH[o] = (int8_t)IH;
        dL[o] = (int8_t)IL;
    }
}

// ---------------- int8 digit GEMM, 128x128 tile, 3-stage cp.async -------------
// MODE 0: gate = a @ wg^T -> g_gf
// MODE 1: up   = a @ wi^T; h = silu(g_gf)*up -> g_hf
// MODE 2: y    = h @ wo^T -> g_y
// 512 thr, 4x4 warps, warp tile 32x32; chunk = 64 k-bytes; pitch 80 B.
#define PITCHB 80
#define PLANEB (128 * PITCHB)     // 10240
#define STAGEB (4 * PLANEB)       // 40960: A_IH, A_IL, B_IH, B_IL
#define STAGES 3
#define SMEMB  (STAGES * STAGEB)  // 122880

template <int MODE>
__global__ void __launch_bounds__(512, 1)
moe_imma() {
    constexpr int K = (MODE == 2) ? HDIM : CDIM;
    constexpr int KT = K / 64;

    extern __shared__ char smem[];
    uint32_t sb = smem_u32(smem);

    int bx = blockIdx.x;
    if (bx >= g_numTiles) return;
    int by = blockIdx.y;
    int e = g_tileE[bx], r0 = g_tileR[bx], off = g_off[e];
    int rowsLeft = g_cnt[e] - r0;
    if (rowsLeft > 128) rowsLeft = 128;
    int nb = by * 128;

    int tid = threadIdx.x, wid = tid >> 5, lane = tid & 31;
    int WM = wid & 3, WN = wid >> 2;
    int gq = lane >> 2, tg = lane & 3;

    const int8_t *srcA0, *srcA1, *srcB0, *srcB1;
    const float *sRow, *sCol;
    if (MODE == 0) {
        srcA0 = g_aIH + (size_t)(off + r0) * CDIM;
        srcA1 = g_aIL + (size_t)(off + r0) * CDIM;
        srcB0 = g_wgIH + ((size_t)e * HDIM + nb) * CDIM;
        srcB1 = g_wgIL + ((size_t)e * HDIM + nb) * CDIM;
        sRow = g_sA; sCol = g_sWg + e * HDIM + nb;
    } else if (MODE == 1) {
        srcA0 = g_aIH + (size_t)(off + r0) * CDIM;
        srcA1 = g_aIL + (size_t)(off + r0) * CDIM;
        srcB0 = g_wiIH + ((size_t)e * HDIM + nb) * CDIM;
        srcB1 = g_wiIL + ((size_t)e * HDIM + nb) * CDIM;
        sRow = g_sA; sCol = g_sWi + e * HDIM + nb;
    } else {
        srcA0 = g_hIH + (size_t)(off + r0) * HDIM;
        srcA1 = g_hIL + (size_t)(off + r0) * HDIM;
        srcB0 = g_woIH + ((size_t)e * CDIM + nb) * HDIM;
        srcB1 = g_woIL + ((size_t)e * CDIM + nb) * HDIM;
        sRow = g_sH; sCol = g_sWo + e * CDIM + nb;
    }

    int lrow = tid >> 2, lch = tid & 3;

    auto load_buf = [&](int buf, int kc) {
        uint32_t base = sb + buf * STAGEB;
        int k0 = kc * 64;
        uint32_t szA = (lrow < rowsLeft) ? 16u : 0u;
        int ra = (lrow < rowsLeft) ? lrow : 0;
        uint32_t doff = lrow * PITCHB + lch * 16;
        size_t goffA = (size_t)ra * K + k0 + lch * 16;
        size_t goffB = (size_t)lrow * K + k0 + lch * 16;
        CP_ASYNC16(base + doff,              srcA0 + goffA, szA);
        CP_ASYNC16(base + PLANEB + doff,     srcA1 + goffA, szA);
        CP_ASYNC16(base + 2 * PLANEB + doff, srcB0 + goffB, 16u);
        CP_ASYNC16(base + 3 * PLANEB + doff, srcB1 + goffB, 16u);
        CP_COMMIT();
    };

    int32_t accH[2][4][4], accX[2][4][4];
#pragma unroll
    for (int a = 0; a < 2; a++)
#pragma unroll
        for (int b = 0; b < 4; b++)
#pragma unroll
            for (int c = 0; c < 4; c++) { accH[a][b][c] = 0; accX[a][b][c] = 0; }

    load_buf(0, 0);
    load_buf(1, 1);

    uint32_t aRowOff = (WM * 32 + (lane & 15)) * PITCHB + (lane >> 4) * 16;
    uint32_t bRowOff = (WN * 32 + (lane & 15)) * PITCHB + (lane >> 4) * 16;

    int cb = 0;
    for (int kc = 0; kc < KT; kc++) {
        if (kc + 1 < KT) { CP_WAIT(1); } else { CP_WAIT(0); }
        __syncthreads();
        if (kc + 2 < KT) {
            int lb = cb + 2; if (lb >= STAGES) lb -= STAGES;
            load_buf(lb, kc + 2);
        }

        uint32_t base = sb + cb * STAGEB;
#pragma unroll
        for (int ks = 0; ks < 2; ks++) {
            uint32_t kOff = ks * 32;
            uint32_t ah[2][4], al[2][4], bh[2][4], bl[2][4];
#pragma unroll
            for (int mi = 0; mi < 2; mi++) {
                ldsm4(ah[mi], base + aRowOff + mi * 16 * PITCHB + kOff);
                ldsm4(al[mi], base + PLANEB + aRowOff + mi * 16 * PITCHB + kOff);
            }
#pragma unroll
            for (int ng = 0; ng < 2; ng++) {
                ldsm4(bh[ng], base + 2 * PLANEB + bRowOff + ng * 16 * PITCHB + kOff);
                ldsm4(bl[ng], base + 3 * PLANEB + bRowOff + ng * 16 * PITCHB + kOff);
            }
#pragma unroll
            for (int mi = 0; mi < 2; mi++)
#pragma unroll
                for (int nj = 0; nj < 4; nj++) {
                    int ng = nj >> 1, ix = nj & 1;
                    mma_s8(accH[mi][nj], ah[mi], bh[ng][ix], bh[ng][ix + 2]);
                    mma_s8(accX[mi][nj], ah[mi], bl[ng][ix], bl[ng][ix + 2]);
                    mma_s8(accX[mi][nj], al[mi], bh[ng][ix], bh[ng][ix + 2]);
                }
        }
        cb++; if (cb >= STAGES) cb = 0;
        __syncthreads();
    }

    // ---- epilogue: y = sRow*sCol*(16384*HH + 128*X) --------------------------
    int grb = off + r0;
#pragma unroll
    for (int mi = 0; mi < 2; mi++) {
#pragma unroll
        for (int half = 0; half < 2; half++) {
            int r = WM * 32 + mi * 16 + gq + half * 8;
            if (r >= rowsLeft) continue;
            size_t grow = (size_t)(grb + r);
            float sR = sRow[grow];
#pragma unroll
            for (int nj = 0; nj < 4; nj++) {
                int cl = WN * 32 + nj * 8 + tg * 2;
                int c = nb + cl;
                float sc0 = sCol[cl], sc1 = sCol[cl + 1];
                int i0 = half * 2;
                float v0 = sR * sc0 * (16384.f * (float)accH[mi][nj][i0] + 128.f * (float)accX[mi][nj][i0]);
                float v1 = sR * sc1 * (16384.f * (float)accH[mi][nj][i0 + 1] + 128.f * (float)accX[mi][nj][i0 + 1]);
                if (MODE == 0) {
                    *(float2*)&g_gf[grow * HDIM + c] = make_float2(v0, v1);
                } else if (MODE == 1) {
                    float2 g = *(const float2*)&g_gf[grow * HDIM + c];
                    float h0 = v0 * g.x / (1.f + __expf(-g.x));
                    float h1 = v1 * g.y / (1.f + __expf(-g.y));
                    *(float2*)&g_hf[grow * HDIM + c] = make_float2(h0, h1);
                } else {
                    *(float2*)&g_y[grow * CDIM + c] = make_float2(v0, v1);
                }
            }
        }
    }
}

// ---------------- combine ----------------------------------------------------
__global__ void combine_kernel(float* __restrict__ out) {
    int gid = blockIdx.x * blockDim.x + threadIdx.x;
    int t = gid >> 8;
    int c4 = (gid & 255) * 4;
    int p0 = g_pairidx[2 * t], p1 = g_pairidx[2 * t + 1];
    float w0 = g_wt[p0], w1 = g_wt[p1];
    float4 y0 = *(const float4*)&g_y[(size_t)p0 * CDIM + c4];
    float4 y1 = *(const float4*)&g_y[(size_t)p1 * CDIM + c4];
    float4 o;
    o.x = w0 * y0.x + w1 * y1.x;
    o.y = w0 * y0.y + w1 * y1.y;
    o.z = w0 * y0.z + w1 * y1.z;
    o.w = w0 * y0.w + w1 * y1.w;
    *(float4*)(out + (size_t)t * CDIM + c4) = o;
}

// ---------------- launch -----------------------------------------------------
#define WQ_SMEM01 (CDIM * 33 * 4)   // 135168
#define WQ_SMEM2  (HDIM * 17 * 4)   // 139264

extern "C" void kernel_launch(void* const* d_in, const int* in_sizes, int n_in,
                              void* d_out, int out_size) {
    const float* x      = (const float*)d_in[0];
    const float* w_gate = (const float*)d_in[1];
    const float* wi     = (const float*)d_in[2];
    const float* wg     = (const float*)d_in[3];
    const float* wo     = (const float*)d_in[4];
    float* out = (float*)d_out;

    cudaFuncSetAttribute(wquant_kernel<0>, cudaFuncAttributeMaxDynamicSharedMemorySize, WQ_SMEM01);
    cudaFuncSetAttribute(wquant_kernel<1>, cudaFuncAttributeMaxDynamicSharedMemorySize, WQ_SMEM01);
    cudaFuncSetAttribute(wquant_kernel<2>, cudaFuncAttributeMaxDynamicSharedMemorySize, WQ_SMEM2);
    cudaFuncSetAttribute(moe_imma<0>, cudaFuncAttributeMaxDynamicSharedMemorySize, SMEMB);
    cudaFuncSetAttribute(moe_imma<1>, cudaFuncAttributeMaxDynamicSharedMemorySize, SMEMB);
    cudaFuncSetAttribute(moe_imma<2>, cudaFuncAttributeMaxDynamicSharedMemorySize, SMEMB);

    gate_kernel<<<NTOK / 8, 256>>>(x, w_gate);
    setup_kernel<<<1, 256>>>();
    xquant_kernel<<<NPAIR, 256>>>(x);

    wquant_kernel<0><<<dim3(HDIM / 32, NEXP), 256, WQ_SMEM01>>>(wg, HDIM);
    wquant_kernel<1><<<dim3(HDIM / 32, NEXP), 256, WQ_SMEM01>>>(wi, HDIM);
    wquant_kernel<2><<<dim3(CDIM / 16, NEXP), 256, WQ_SMEM2>>>(wo, CDIM);

    moe_imma<0><<<dim3(MT_MAX, HDIM / 128), 512, SMEMB>>>();
    moe_imma<1><<<dim3(MT_MAX, HDIM / 128), 512, SMEMB>>>();
    hquant_kernel<<<NPAIR, 256>>>();
    moe_imma<2><<<dim3(MT_MAX, CDIM / 128), 512, SMEMB>>>();

    combine_kernel<<<NTOK * (CDIM / 4) / 256, 256>>>(out);
}

// round 10
// speedup vs baseline: 4.4180x; 4.4180x over previous
#include <cuda_runtime.h>
#include <cuda_fp16.h>
#include <cstdint>
#include <math.h>

// ---------------- problem constants ------------------------------------------
#define NTOK 8192
#define CDIM 1024
#define HDIM 2048
#define NEXP 8
#define NPAIR (NTOK * 2)
#define BM 128
#define MT_MAX 136

// ---------------- scratch ----------------------------------------------------
__device__ __half g_ax[(size_t)NPAIR * CDIM];             // gathered x, fp16
__device__ __half g_wgT[(size_t)NEXP * HDIM * CDIM];      // wg^T [E][H][C]
__device__ __half g_wiT[(size_t)NEXP * HDIM * CDIM];      // wi^T [E][H][C]
__device__ __half g_woT[(size_t)NEXP * CDIM * HDIM];      // wo^T [E][C][H]
__device__ __half g_h[(size_t)NPAIR * HDIM];              // h = silu(gate)*up
__device__ float  g_y[(size_t)NPAIR * CDIM];

__device__ int   g_sel[NTOK * 2];
__device__ float g_selw[NTOK * 2];
__device__ int   g_tok[NPAIR];
__device__ float g_wt[NPAIR];
__device__ int   g_pairidx[NTOK * 2];
__device__ int   g_cnt[NEXP];
__device__ int   g_off[NEXP];
__device__ int   g_tileE[MT_MAX];
__device__ int   g_tileR[MT_MAX];
__device__ int   g_numTiles;

// ---------------- PTX helpers -------------------------------------------------
__device__ __forceinline__ uint32_t smem_u32(const void* p) {
    uint32_t a;
    asm("{ .reg .u64 t; cvta.to.shared.u64 t, %1; cvt.u32.u64 %0, t; }" : "=r"(a) : "l"(p));
    return a;
}
__device__ __forceinline__ void ldsm4(uint32_t* r, uint32_t addr) {
    asm volatile("ldmatrix.sync.aligned.m8n8.x4.shared.b16 {%0,%1,%2,%3}, [%4];"
                 : "=r"(r[0]), "=r"(r[1]), "=r"(r[2]), "=r"(r[3]) : "r"(addr));
}
__device__ __forceinline__ void mma_f16(float* d, const uint32_t* a, uint32_t b0, uint32_t b1) {
    asm volatile("mma.sync.aligned.m16n8k16.row.col.f32.f16.f16.f32 "
                 "{%0,%1,%2,%3}, {%4,%5,%6,%7}, {%8,%9}, {%0,%1,%2,%3};"
                 : "+f"(d[0]), "+f"(d[1]), "+f"(d[2]), "+f"(d[3])
                 : "r"(a[0]), "r"(a[1]), "r"(a[2]), "r"(a[3]), "r"(b0), "r"(b1));
}
#define CP_ASYNC16(dst, src, sz) \
    asm volatile("cp.async.cg.shared.global [%0], [%1], 16, %2;" :: "r"(dst), "l"(src), "r"(sz) : "memory")
#define CP_COMMIT() asm volatile("cp.async.commit_group;" ::: "memory")
#define CP_WAIT(n)  asm volatile("cp.async.wait_group %0;" :: "n"(n) : "memory")

// ---------------- gating -----------------------------------------------------
__global__ void gate_kernel(const float* __restrict__ x, const float* __restrict__ wgate) {
    int warp = (blockIdx.x * blockDim.x + threadIdx.x) >> 5;
    int lane = threadIdx.x & 31;
    if (warp >= NTOK) return;
    const float* xr = x + (size_t)warp * CDIM;
    float acc[NEXP];
#pragma unroll
    for (int e = 0; e < NEXP; e++) acc[e] = 0.f;
    for (int i = lane * 4; i < CDIM; i += 128) {
        float4 xv = *(const float4*)(xr + i);
        float xs[4] = {xv.x, xv.y, xv.z, xv.w};
#pragma unroll
        for (int j = 0; j < 4; j++) {
            const float* wr = wgate + (size_t)(i + j) * NEXP;
#pragma unroll
            for (int e = 0; e < NEXP; e++) acc[e] += xs[j] * wr[e];
        }
    }
#pragma unroll
    for (int e = 0; e < NEXP; e++)
#pragma unroll
        for (int d = 16; d > 0; d >>= 1) acc[e] += __shfl_down_sync(0xffffffffu, acc[e], d);
    if (lane == 0) {
        float m = acc[0];
#pragma unroll
        for (int e = 1; e < NEXP; e++) m = fmaxf(m, acc[e]);
        float p[NEXP]; float s = 0.f;
#pragma unroll
        for (int e = 0; e < NEXP; e++) { p[e] = expf(acc[e] - m); s += p[e]; }
        float inv = 1.f / s;
#pragma unroll
        for (int e = 0; e < NEXP; e++) p[e] *= inv;
        int i1 = 0;
#pragma unroll
        for (int e = 1; e < NEXP; e++) if (p[e] > p[i1]) i1 = e;
        int i2 = (i1 == 0) ? 1 : 0;
#pragma unroll
        for (int e = 0; e < NEXP; e++) if (e != i1 && p[e] > p[i2]) i2 = e;
        g_sel[2 * warp] = i1;     g_selw[2 * warp] = p[i1];
        g_sel[2 * warp + 1] = i2; g_selw[2 * warp + 1] = p[i2];
    }
}

// ---------------- routing build ----------------------------------------------
__global__ void setup_kernel() {
    __shared__ int scnt[NEXP], soff[NEXP], wsum[8];
    __shared__ int carry_s;
    int tid = threadIdx.x, lane = tid & 31, wid = tid >> 5;
    if (tid < NEXP) scnt[tid] = 0;
    __syncthreads();
    for (int t = tid; t < NTOK; t += 256) {
        atomicAdd(&scnt[g_sel[2 * t]], 1);
        atomicAdd(&scnt[g_sel[2 * t + 1]], 1);
    }
    __syncthreads();
    if (tid == 0) {
        int o = 0, nt = 0;
        for (int e = 0; e < NEXP; e++) {
            g_cnt[e] = scnt[e]; g_off[e] = o; soff[e] = o;
            for (int r = 0; r < scnt[e]; r += BM) { g_tileE[nt] = e; g_tileR[nt] = r; nt++; }
            o += scnt[e];
        }
        g_numTiles = nt;
    }
    __syncthreads();
    for (int e = 0; e < NEXP; e++) {
        if (tid == 0) carry_s = 0;
        __syncthreads();
        int base_off = soff[e];
        for (int base = 0; base < NTOK; base += 256) {
            int t = base + tid;
            int slot = (g_sel[2 * t] == e) ? 0 : ((g_sel[2 * t + 1] == e) ? 1 : -1);
            int f = (slot >= 0) ? 1 : 0;
            int v = f;
#pragma unroll
            for (int d = 1; d < 32; d <<= 1) {
                int u = __shfl_up_sync(0xffffffffu, v, d);
                if (lane >= d) v += u;
            }
            if (lane == 31) wsum[wid] = v;
            __syncthreads();
            int wbase = 0, tot = 0;
#pragma unroll
            for (int w = 0; w < 8; w++) { if (w < wid) wbase += wsum[w]; tot += wsum[w]; }
            if (f) {
                int p = base_off + carry_s + wbase + v - 1;
                g_tok[p] = t;
                g_wt[p] = g_selw[2 * t + slot];
                g_pairidx[2 * t + slot] = p;
            }
            __syncthreads();
            if (tid == 0) carry_s += tot;
            __syncthreads();
        }
    }
}

// ---------------- weight transpose + fp16 convert (device-selected dst) -------
template <int W>
__global__ void tconv_kernel(const float* __restrict__ src, int K, int S) {
    __half* dst = (W == 0) ? g_wgT : (W == 1) ? g_wiT : g_woT;
    __shared__ float t[32][33];
    int e = blockIdx.z;
    int k0 = blockIdx.x * 32, s0 = blockIdx.y * 32;
    const float* sp = src + (size_t)e * K * S;
    int tx = threadIdx.x, ty = threadIdx.y;
#pragma unroll
    for (int j = 0; j < 32; j += 8)
        t[ty + j][tx] = sp[(size_t)(k0 + ty + j) * S + s0 + tx];
    __syncthreads();
    size_t dbase = (size_t)e * S * K;
#pragma unroll
    for (int j = 0; j < 32; j += 8)
        dst[dbase + (size_t)(s0 + ty + j) * K + k0 + tx] = __float2half_rn(t[tx][ty + j]);
}

// ---------------- activation gather + fp16 convert ----------------------------
__global__ void gather_kernel(const float* __restrict__ x) {
    int p = blockIdx.x;
    int t = g_tok[p];
    const float* src = x + (size_t)t * CDIM;
    size_t dst = (size_t)p * CDIM;
    for (int i = threadIdx.x; i < CDIM; i += 256)
        g_ax[dst + i] = __float2half_rn(src[i]);
}

// ---------------- fp16 mma GEMM, 128x128 tile, 3-stage cp.async ---------------
// MODE 0 (fused): gate = ax@wgT^T, up = ax@wiT^T, h = silu(gate)*up -> g_h fp16
// MODE 2 (down):  y = h@woT^T -> g_y fp32
// 512 threads, 4m x 4n warps, warp tile 32x32, ONE mma per fragment (fp16).
#define PITCHB 80
#define PLANEB (128 * PITCHB)   // 10240
#define STAGES 3

template <int MODE>
__global__ void __launch_bounds__(512, 1)
moe_hmma() {
    constexpr int K = (MODE == 0) ? CDIM : HDIM;
    constexpr int KT = K / 32;
    constexpr int NW = (MODE == 0) ? 2 : 1;       // weight operands
    constexpr int STAGEB = (1 + NW) * PLANEB;     // A + B planes

    extern __shared__ char smem[];
    uint32_t sb = smem_u32(smem);

    int bx = blockIdx.x;
    if (bx >= g_numTiles) return;
    int by = blockIdx.y;
    int e = g_tileE[bx], r0 = g_tileR[bx], off = g_off[e];
    int rowsLeft = g_cnt[e] - r0;
    if (rowsLeft > 128) rowsLeft = 128;
    int nb = by * 128;

    int tid = threadIdx.x, wid = tid >> 5, lane = tid & 31;
    int WM = wid & 3, WN = wid >> 2;
    int gq = lane >> 2, tg = lane & 3;

    const __half* srcA;
    const __half* srcB[2];
    if (MODE == 0) {
        srcA = g_ax + (size_t)(off + r0) * CDIM;
        srcB[0] = g_wgT + ((size_t)e * HDIM + nb) * CDIM;
        srcB[1] = g_wiT + ((size_t)e * HDIM + nb) * CDIM;
    } else {
        srcA = g_h + (size_t)(off + r0) * HDIM;
        srcB[0] = g_woT + ((size_t)e * CDIM + nb) * HDIM;
    }

    int lrow = tid >> 2, lch = tid & 3;    // 512 thr -> 1 chunk/plane/thread

    auto load_buf = [&](int buf, int kc) {
        uint32_t base = sb + buf * STAGEB;
        int k0 = kc * 32;
        uint32_t doff = lrow * PITCHB + lch * 16;
        uint32_t szA = (lrow < rowsLeft) ? 16u : 0u;
        int ra = (lrow < rowsLeft) ? lrow : 0;
        CP_ASYNC16(base + doff, srcA + (size_t)ra * K + k0 + lch * 8, szA);
#pragma unroll
        for (int p = 0; p < NW; p++)
            CP_ASYNC16(base + (1 + p) * PLANEB + doff,
                       srcB[p] + (size_t)lrow * K + k0 + lch * 8, 16u);
        CP_COMMIT();
    };

    float acc[NW][2][4][4];
#pragma unroll
    for (int w = 0; w < NW; w++)
#pragma unroll
        for (int a = 0; a < 2; a++)
#pragma unroll
            for (int b = 0; b < 4; b++)
#pragma unroll
                for (int c = 0; c < 4; c++) acc[w][a][b][c] = 0.f;

    load_buf(0, 0);
    load_buf(1, 1);

    uint32_t aRowOff = (WM * 32 + (lane & 15)) * PITCHB + (lane >> 4) * 16;
    uint32_t bRowOff = (WN * 32 + (lane & 15)) * PITCHB + (lane >> 4) * 16;

    int cb = 0;
    for (int kc = 0; kc < KT; kc++) {
        if (kc + 1 < KT) { CP_WAIT(1); } else { CP_WAIT(0); }
        __syncthreads();
        if (kc + 2 < KT) {
            int lb = cb + 2; if (lb >= STAGES) lb -= STAGES;
            load_buf(lb, kc + 2);
        }

        uint32_t base = sb + cb * STAGEB;
#pragma unroll
        for (int ks = 0; ks < 2; ks++) {
            uint32_t kOff = ks * 32;
            uint32_t a[2][4];
#pragma unroll
            for (int mi = 0; mi < 2; mi++)
                ldsm4(a[mi], base + aRowOff + mi * 16 * PITCHB + kOff);
#pragma unroll
            for (int w = 0; w < NW; w++) {
                uint32_t b[2][4];
                uint32_t bBase = base + (1 + w) * PLANEB;
#pragma unroll
                for (int ng = 0; ng < 2; ng++)
                    ldsm4(b[ng], bBase + bRowOff + ng * 16 * PITCHB + kOff);
#pragma unroll
                for (int mi = 0; mi < 2; mi++)
#pragma unroll
                    for (int nj = 0; nj < 4; nj++) {
                        int ng = nj >> 1, ix = nj & 1;
                        mma_f16(acc[w][mi][nj], a[mi], b[ng][ix], b[ng][ix + 2]);
                    }
            }
        }
        cb++; if (cb >= STAGES) cb = 0;
        __syncthreads();
    }

    // ---- epilogue ----
    int grb = off + r0;
#pragma unroll
    for (int mi = 0; mi < 2; mi++) {
#pragma unroll
        for (int half = 0; half < 2; half++) {
            int r = WM * 32 + mi * 16 + gq + half * 8;
            if (r >= rowsLeft) continue;
            size_t grow = (size_t)(grb + r);
#pragma unroll
            for (int nj = 0; nj < 4; nj++) {
                int c = nb + WN * 32 + nj * 8 + tg * 2;
                if (MODE == 0) {
                    float gt0 = acc[0][mi][nj][half * 2 + 0];
                    float gt1 = acc[0][mi][nj][half * 2 + 1];
                    float up0 = acc[1][mi][nj][half * 2 + 0];
                    float up1 = acc[1][mi][nj][half * 2 + 1];
                    float h0 = up0 * gt0 / (1.f + __expf(-gt0));
                    float h1 = up1 * gt1 / (1.f + __expf(-gt1));
                    __half ph0 = __float2half_rn(h0);
                    __half ph1 = __float2half_rn(h1);
                    uint32_t pk = ((uint32_t)__half_as_ushort(ph1) << 16) | __half_as_ushort(ph0);
                    *(uint32_t*)&g_h[grow * HDIM + c] = pk;
                } else {
                    float d0 = acc[0][mi][nj][half * 2 + 0];
                    float d1 = acc[0][mi][nj][half * 2 + 1];
                    *(float2*)&g_y[grow * CDIM + c] = make_float2(d0, d1);
                }
            }
        }
    }
}

// ---------------- combine ----------------------------------------------------
__global__ void combine_kernel(float* __restrict__ out) {
    int gid = blockIdx.x * blockDim.x + threadIdx.x;
    int t = gid >> 8;
    int c4 = (gid & 255) * 4;
    int p0 = g_pairidx[2 * t], p1 = g_pairidx[2 * t + 1];
    float w0 = g_wt[p0], w1 = g_wt[p1];
    float4 y0 = *(const float4*)&g_y[(size_t)p0 * CDIM + c4];
    float4 y1 = *(const float4*)&g_y[(size_t)p1 * CDIM + c4];
    float4 o;
    o.x = w0 * y0.x + w1 * y1.x;
    o.y = w0 * y0.y + w1 * y1.y;
    o.z = w0 * y0.z + w1 * y1.z;
    o.w = w0 * y0.w + w1 * y1.w;
    *(float4*)(out + (size_t)t * CDIM + c4) = o;
}

// ---------------- launch -----------------------------------------------------
#define SMEM0 (STAGES * 3 * PLANEB)   // 92160
#define SMEM2 (STAGES * 2 * PLANEB)   // 61440

extern "C" void kernel_launch(void* const* d_in, const int* in_sizes, int n_in,
                              void* d_out, int out_size) {
    const float* x      = (const float*)d_in[0];
    const float* w_gate = (const float*)d_in[1];
    const float* wi     = (const float*)d_in[2];
    const float* wg     = (const float*)d_in[3];
    const float* wo     = (const float*)d_in[4];
    float* out = (float*)d_out;

    cudaFuncSetAttribute(moe_hmma<0>, cudaFuncAttributeMaxDynamicSharedMemorySize, SMEM0);
    cudaFuncSetAttribute(moe_hmma<2>, cudaFuncAttributeMaxDynamicSharedMemorySize, SMEM2);

    gate_kernel<<<NTOK / 8, 256>>>(x, w_gate);
    setup_kernel<<<1, 256>>>();
    gather_kernel<<<NPAIR, 256>>>(x);

    dim3 tb(32, 8);
    tconv_kernel<0><<<dim3(CDIM / 32, HDIM / 32, NEXP), tb>>>(wg, CDIM, HDIM);
    tconv_kernel<1><<<dim3(CDIM / 32, HDIM / 32, NEXP), tb>>>(wi, CDIM, HDIM);
    tconv_kernel<2><<<dim3(HDIM / 32, CDIM / 32, NEXP), tb>>>(wo, HDIM, CDIM);

    moe_hmma<0><<<dim3(MT_MAX, HDIM / 128), 512, SMEM0>>>();
    moe_hmma<2><<<dim3(MT_MAX, CDIM / 128), 512, SMEM2>>>();

    combine_kernel<<<NTOK * (CDIM / 4) / 256, 256>>>(out);
}

// round 11
// speedup vs baseline: 4.8916x; 1.1072x over previous
#include <cuda_runtime.h>
#include <cuda_fp16.h>
#include <cstdint>
#include <math.h>

// ---------------- problem constants ------------------------------------------
#define NTOK 8192
#define CDIM 1024
#define HDIM 2048
#define NEXP 8
#define NPAIR (NTOK * 2)
#define BM 128
#define MT_MAX 136

// ---------------- scratch ----------------------------------------------------
__device__ __half g_xh[(size_t)NTOK * CDIM];              // x in fp16 (per token)
__device__ __half g_wgT[(size_t)NEXP * HDIM * CDIM];
__device__ __half g_wiT[(size_t)NEXP * HDIM * CDIM];
__device__ __half g_woT[(size_t)NEXP * CDIM * HDIM];
__device__ __half g_h[(size_t)NPAIR * HDIM];
__device__ float  g_y[(size_t)NPAIR * CDIM];

__device__ int   g_sel[NTOK * 2];
__device__ float g_selw[NTOK * 2];
__device__ int   g_tok[NPAIR];
__device__ float g_wt[NPAIR];
__device__ int   g_pairidx[NTOK * 2];
__device__ int   g_cnt[NEXP];
__device__ int   g_off[NEXP];
__device__ int   g_tileE[MT_MAX];
__device__ int   g_tileR[MT_MAX];
__device__ int   g_numTiles;

// ---------------- PTX helpers -------------------------------------------------
__device__ __forceinline__ uint32_t smem_u32(const void* p) {
    uint32_t a;
    asm("{ .reg .u64 t; cvta.to.shared.u64 t, %1; cvt.u32.u64 %0, t; }" : "=r"(a) : "l"(p));
    return a;
}
__device__ __forceinline__ void ldsm4(uint32_t* r, uint32_t addr) {
    asm volatile("ldmatrix.sync.aligned.m8n8.x4.shared.b16 {%0,%1,%2,%3}, [%4];"
                 : "=r"(r[0]), "=r"(r[1]), "=r"(r[2]), "=r"(r[3]) : "r"(addr));
}
__device__ __forceinline__ void mma_f16(float* d, const uint32_t* a, uint32_t b0, uint32_t b1) {
    asm volatile("mma.sync.aligned.m16n8k16.row.col.f32.f16.f16.f32 "
                 "{%0,%1,%2,%3}, {%4,%5,%6,%7}, {%8,%9}, {%0,%1,%2,%3};"
                 : "+f"(d[0]), "+f"(d[1]), "+f"(d[2]), "+f"(d[3])
                 : "r"(a[0]), "r"(a[1]), "r"(a[2]), "r"(a[3]), "r"(b0), "r"(b1));
}
#define CP_ASYNC16(dst, src, sz) \
    asm volatile("cp.async.cg.shared.global [%0], [%1], 16, %2;" :: "r"(dst), "l"(src), "r"(sz) : "memory")
#define CP_COMMIT() asm volatile("cp.async.commit_group;" ::: "memory")
#define CP_WAIT(n)  asm volatile("cp.async.wait_group %0;" :: "n"(n) : "memory")

// ---------------- gating -----------------------------------------------------
__global__ void gate_kernel(const float* __restrict__ x, const float* __restrict__ wgate) {
    int warp = (blockIdx.x * blockDim.x + threadIdx.x) >> 5;
    int lane = threadIdx.x & 31;
    if (warp >= NTOK) return;
    const float* xr = x + (size_t)warp * CDIM;
    float acc[NEXP];
#pragma unroll
    for (int e = 0; e < NEXP; e++) acc[e] = 0.f;
    for (int i = lane * 4; i < CDIM; i += 128) {
        float4 xv = *(const float4*)(xr + i);
        float xs[4] = {xv.x, xv.y, xv.z, xv.w};
#pragma unroll
        for (int j = 0; j < 4; j++) {
            const float* wr = wgate + (size_t)(i + j) * NEXP;
#pragma unroll
            for (int e = 0; e < NEXP; e++) acc[e] += xs[j] * wr[e];
        }
    }
#pragma unroll
    for (int e = 0; e < NEXP; e++)
#pragma unroll
        for (int d = 16; d > 0; d >>= 1) acc[e] += __shfl_down_sync(0xffffffffu, acc[e], d);
    if (lane == 0) {
        float m = acc[0];
#pragma unroll
        for (int e = 1; e < NEXP; e++) m = fmaxf(m, acc[e]);
        float p[NEXP]; float s = 0.f;
#pragma unroll
        for (int e = 0; e < NEXP; e++) { p[e] = expf(acc[e] - m); s += p[e]; }
        float inv = 1.f / s;
#pragma unroll
        for (int e = 0; e < NEXP; e++) p[e] *= inv;
        int i1 = 0;
#pragma unroll
        for (int e = 1; e < NEXP; e++) if (p[e] > p[i1]) i1 = e;
        int i2 = (i1 == 0) ? 1 : 0;
#pragma unroll
        for (int e = 0; e < NEXP; e++) if (e != i1 && p[e] > p[i2]) i2 = e;
        g_sel[2 * warp] = i1;     g_selw[2 * warp] = p[i1];
        g_sel[2 * warp + 1] = i2; g_selw[2 * warp + 1] = p[i2];
    }
}

// ---------------- routing: parallel count / offsets / stable place ------------
__global__ void cnt_kernel() {
    int e = blockIdx.x, tid = threadIdx.x, lane = tid & 31, wid = tid >> 5;
    __shared__ int red[32];
    int c = 0;
    for (int t = tid; t < NTOK; t += 1024)
        c += (g_sel[2 * t] == e) + (g_sel[2 * t + 1] == e);
#pragma unroll
    for (int d = 16; d > 0; d >>= 1) c += __shfl_down_sync(0xffffffffu, c, d);
    if (lane == 0) red[wid] = c;
    __syncthreads();
    if (wid == 0) {
        int v = red[lane];
#pragma unroll
        for (int d = 16; d > 0; d >>= 1) v += __shfl_down_sync(0xffffffffu, v, d);
        if (lane == 0) g_cnt[e] = v;
    }
}

__global__ void offs_kernel() {
    int o = 0, nt = 0;
    for (int e = 0; e < NEXP; e++) {
        g_off[e] = o;
        for (int r = 0; r < g_cnt[e]; r += BM) { g_tileE[nt] = e; g_tileR[nt] = r; nt++; }
        o += g_cnt[e];
    }
    g_numTiles = nt;
}

__global__ void place_kernel() {
    int e = blockIdx.x;
    __shared__ int wsum[32];
    __shared__ int carry;
    int tid = threadIdx.x, lane = tid & 31, wid = tid >> 5;
    if (tid == 0) carry = 0;
    __syncthreads();
    int base_off = g_off[e];
    for (int base = 0; base < NTOK; base += 1024) {
        int t = base + tid;
        int slot = (g_sel[2 * t] == e) ? 0 : ((g_sel[2 * t + 1] == e) ? 1 : -1);
        int f = (slot >= 0) ? 1 : 0;
        int v = f;
#pragma unroll
        for (int d = 1; d < 32; d <<= 1) {
            int u = __shfl_up_sync(0xffffffffu, v, d);
            if (lane >= d) v += u;
        }
        if (lane == 31) wsum[wid] = v;
        __syncthreads();
        int wbase = 0, tot = 0;
#pragma unroll
        for (int w = 0; w < 32; w++) { if (w < wid) wbase += wsum[w]; tot += wsum[w]; }
        if (f) {
            int p = base_off + carry + wbase + v - 1;
            g_tok[p] = t;
            g_wt[p] = g_selw[2 * t + slot];
            g_pairidx[2 * t + slot] = p;
        }
        __syncthreads();
        if (tid == 0) carry += tot;
        __syncthreads();
    }
}

// ---------------- x -> fp16 (per token, no pair duplication) ------------------
__global__ void xconv_kernel(const float* __restrict__ x) {
    size_t i = (size_t)blockIdx.x * 512 + threadIdx.x;
    float2 v = ((const float2*)x)[i];
    ((__half2*)g_xh)[i] = __floats2half2_rn(v.x, v.y);
}

// ---------------- weight transpose + fp16 (64K x 32S tiles, half2 stores) -----
template <int W>
__global__ void tconv_kernel(const float* __restrict__ src, int K, int S) {
    __half* dst = (W == 0) ? g_wgT : (W == 1) ? g_wiT : g_woT;
    __shared__ float t[64][33];
    int e = blockIdx.z;
    int k0 = blockIdx.x * 64, s0 = blockIdx.y * 32;
    const float* sp = src + (size_t)e * K * S;
    int tx = threadIdx.x, ty = threadIdx.y;     // (32, 8)
#pragma unroll
    for (int j = 0; j < 64; j += 8)
        t[ty + j][tx] = sp[(size_t)(k0 + ty + j) * S + s0 + tx];
    __syncthreads();
    size_t dbase = (size_t)e * S * K;
#pragma unroll
    for (int j = 0; j < 32; j += 8) {
        int s = s0 + ty + j;
        __half2 h = __floats2half2_rn(t[tx * 2][ty + j], t[tx * 2 + 1][ty + j]);
        *(__half2*)&dst[dbase + (size_t)s * K + k0 + tx * 2] = h;
    }
}

// ---------------- fp16 mma GEMM, 128x128 tile, 3-stage cp.async ---------------
// MODE 0 (fused): gate/up from gathered x rows (token indirection in cp.async)
// MODE 2 (down):  y = h @ woT^T
#define PITCHB 80
#define PLANEB (128 * PITCHB)   // 10240
#define STAGES 3

template <int MODE>
__global__ void __launch_bounds__(512, 1)
moe_hmma() {
    constexpr int K = (MODE == 0) ? CDIM : HDIM;
    constexpr int KT = K / 32;
    constexpr int NW = (MODE == 0) ? 2 : 1;
    constexpr int STAGEB = (1 + NW) * PLANEB;

    extern __shared__ char smem[];
    uint32_t sb = smem_u32(smem);

    int bx = blockIdx.x;
    if (bx >= g_numTiles) return;
    int by = blockIdx.y;
    int e = g_tileE[bx], r0 = g_tileR[bx], off = g_off[e];
    int rowsLeft = g_cnt[e] - r0;
    if (rowsLeft > 128) rowsLeft = 128;
    int nb = by * 128;

    int tid = threadIdx.x, wid = tid >> 5, lane = tid & 31;
    int WM = wid & 3, WN = wid >> 2;
    int gq = lane >> 2, tg = lane & 3;

    const __half* srcB[2];
    if (MODE == 0) {
        srcB[0] = g_wgT + ((size_t)e * HDIM + nb) * CDIM;
        srcB[1] = g_wiT + ((size_t)e * HDIM + nb) * CDIM;
    } else {
        srcB[0] = g_woT + ((size_t)e * CDIM + nb) * HDIM;
    }

    int lrow = tid >> 2, lch = tid & 3;
    bool aval = lrow < rowsLeft;
    int ra = aval ? lrow : 0;
    const __half* aRowPtr;
    if (MODE == 0) {
        int tok = g_tok[off + r0 + ra];
        aRowPtr = g_xh + (size_t)tok * CDIM;
    } else {
        aRowPtr = g_h + (size_t)(off + r0 + ra) * HDIM;
    }
    uint32_t szA = aval ? 16u : 0u;

    auto load_buf = [&](int buf, int kc) {
        uint32_t base = sb + buf * STAGEB;
        int k0 = kc * 32;
        uint32_t doff = lrow * PITCHB + lch * 16;
        CP_ASYNC16(base + doff, aRowPtr + k0 + lch * 8, szA);
#pragma unroll
        for (int p = 0; p < NW; p++)
            CP_ASYNC16(base + (1 + p) * PLANEB + doff,
                       srcB[p] + (size_t)lrow * K + k0 + lch * 8, 16u);
        CP_COMMIT();
    };

    float acc[NW][2][4][4];
#pragma unroll
    for (int w = 0; w < NW; w++)
#pragma unroll
        for (int a = 0; a < 2; a++)
#pragma unroll
            for (int b = 0; b < 4; b++)
#pragma unroll
                for (int c = 0; c < 4; c++) acc[w][a][b][c] = 0.f;

    load_buf(0, 0);
    load_buf(1, 1);

    uint32_t aRowOff = (WM * 32 + (lane & 15)) * PITCHB + (lane >> 4) * 16;
    uint32_t bRowOff = (WN * 32 + (lane & 15)) * PITCHB + (lane >> 4) * 16;

    int cb = 0;
    for (int kc = 0; kc < KT; kc++) {
        if (kc + 1 < KT) { CP_WAIT(1); } else { CP_WAIT(0); }
        __syncthreads();
        if (kc + 2 < KT) {
            int lb = cb + 2; if (lb >= STAGES) lb -= STAGES;
            load_buf(lb, kc + 2);
        }

        uint32_t base = sb + cb * STAGEB;
#pragma unroll
        for (int ks = 0; ks < 2; ks++) {
            uint32_t kOff = ks * 32;
            uint32_t a[2][4];
#pragma unroll
            for (int mi = 0; mi < 2; mi++)
                ldsm4(a[mi], base + aRowOff + mi * 16 * PITCHB + kOff);
#pragma unroll
            for (int w = 0; w < NW; w++) {
                uint32_t b[2][4];
                uint32_t bBase = base + (1 + w) * PLANEB;
#pragma unroll
                for (int ng = 0; ng < 2; ng++)
                    ldsm4(b[ng], bBase + bRowOff + ng * 16 * PITCHB + kOff);
#pragma unroll
                for (int mi = 0; mi < 2; mi++)
#pragma unroll
                    for (int nj = 0; nj < 4; nj++) {
                        int ng = nj >> 1, ix = nj & 1;
                        mma_f16(acc[w][mi][nj], a[mi], b[ng][ix], b[ng][ix + 2]);
                    }
            }
        }
        cb++; if (cb >= STAGES) cb = 0;
        __syncthreads();
    }

    // ---- epilogue ----
    int grb = off + r0;
#pragma unroll
    for (int mi = 0; mi < 2; mi++) {
#pragma unroll
        for (int half = 0; half < 2; half++) {
            int r = WM * 32 + mi * 16 + gq + half * 8;
            if (r >= rowsLeft) continue;
            size_t grow = (size_t)(grb + r);
#pragma unroll
            for (int nj = 0; nj < 4; nj++) {
                int c = nb + WN * 32 + nj * 8 + tg * 2;
                if (MODE == 0) {
                    float gt0 = acc[0][mi][nj][half * 2 + 0];
                    float gt1 = acc[0][mi][nj][half * 2 + 1];
                    float up0 = acc[1][mi][nj][half * 2 + 0];
                    float up1 = acc[1][mi][nj][half * 2 + 1];
                    float h0 = up0 * gt0 / (1.f + __expf(-gt0));
                    float h1 = up1 * gt1 / (1.f + __expf(-gt1));
                    __half ph0 = __float2half_rn(h0);
                    __half ph1 = __float2half_rn(h1);
                    uint32_t pk = ((uint32_t)__half_as_ushort(ph1) << 16) | __half_as_ushort(ph0);
                    *(uint32_t*)&g_h[grow * HDIM + c] = pk;
                } else {
                    float d0 = acc[0][mi][nj][half * 2 + 0];
                    float d1 = acc[0][mi][nj][half * 2 + 1];
                    *(float2*)&g_y[grow * CDIM + c] = make_float2(d0, d1);
                }
            }
        }
    }
}

// ---------------- combine ----------------------------------------------------
__global__ void combine_kernel(float* __restrict__ out) {
    int gid = blockIdx.x * blockDim.x + threadIdx.x;
    int t = gid >> 8;
    int c4 = (gid & 255) * 4;
    int p0 = g_pairidx[2 * t], p1 = g_pairidx[2 * t + 1];
    float w0 = g_wt[p0], w1 = g_wt[p1];
    float4 y0 = *(const float4*)&g_y[(size_t)p0 * CDIM + c4];
    float4 y1 = *(const float4*)&g_y[(size_t)p1 * CDIM + c4];
    float4 o;
    o.x = w0 * y0.x + w1 * y1.x;
    o.y = w0 * y0.y + w1 * y1.y;
    o.z = w0 * y0.z + w1 * y1.z;
    o.w = w0 * y0.w + w1 * y1.w;
    *(float4*)(out + (size_t)t * CDIM + c4) = o;
}

// ---------------- launch -----------------------------------------------------
#define SMEM0 (STAGES * 3 * PLANEB)   // 92160
#define SMEM2 (STAGES * 2 * PLANEB)   // 61440

extern "C" void kernel_launch(void* const* d_in, const int* in_sizes, int n_in,
                              void* d_out, int out_size) {
    const float* x      = (const float*)d_in[0];
    const float* w_gate = (const float*)d_in[1];
    const float* wi     = (const float*)d_in[2];
    const float* wg     = (const float*)d_in[3];
    const float* wo     = (const float*)d_in[4];
    float* out = (float*)d_out;

    cudaFuncSetAttribute(moe_hmma<0>, cudaFuncAttributeMaxDynamicSharedMemorySize, SMEM0);
    cudaFuncSetAttribute(moe_hmma<2>, cudaFuncAttributeMaxDynamicSharedMemorySize, SMEM2);

    gate_kernel<<<NTOK / 8, 256>>>(x, w_gate);
    cnt_kernel<<<NEXP, 1024>>>();
    offs_kernel<<<1, 1>>>();
    place_kernel<<<NEXP, 1024>>>();
    xconv_kernel<<<NTOK * CDIM / 1024, 512>>>(x);

    dim3 tb(32, 8);
    tconv_kernel<0><<<dim3(CDIM / 64, HDIM / 32, NEXP), tb>>>(wg, CDIM, HDIM);
    tconv_kernel<1><<<dim3(CDIM / 64, HDIM / 32, NEXP), tb>>>(wi, CDIM, HDIM);
    tconv_kernel<2><<<dim3(HDIM / 64, CDIM / 32, NEXP), tb>>>(wo, HDIM, CDIM);

    moe_hmma<0><<<dim3(MT_MAX, HDIM / 128), 512, SMEM0>>>();
    moe_hmma<2><<<dim3(MT_MAX, CDIM / 128), 512, SMEM2>>>();

    combine_kernel<<<NTOK * (CDIM / 4) / 256, 256>>>(out);
}